// round 2
// baseline (speedup 1.0000x reference)
#include <cuda_runtime.h>
#include <cuda_fp16.h>
#include <cstdint>
#include <cstddef>

#define BATCH 16384
#define NF 39
#define NE 64
#define FE 2496            // NF*NE
#define ND 400
#define VOC 26000

// ---------------- device scratch (static: no allocations allowed) ----------------
static __device__ __half g_embed[(size_t)BATCH * FE];   // gated embeddings, fp16
static __device__ __half g_h1[(size_t)BATCH * ND];
static __device__ __half g_h2[(size_t)BATCH * ND];
static __device__ __half g_h3[(size_t)BATCH * ND];
static __device__ float  g_scalar[BATCH];               // fm per sample
static __device__ __half g_W1h[FE * ND];
static __device__ __half g_W2h[ND * ND];
static __device__ __half g_W3h[ND * ND];
static __device__ __half g_Wth[NF * NE * NE];
static __device__ float  g_bf1[ND], g_bf2[ND], g_bf3[ND];
static __device__ float  g_sv[NF * NE];

// ---------------- mma.sync m16n8k16 fp16 -> fp32 ----------------
__device__ __forceinline__ void mma16816(float& c0, float& c1, float& c2, float& c3,
                                         uint32_t a0, uint32_t a1, uint32_t a2, uint32_t a3,
                                         uint32_t b0, uint32_t b1) {
    asm volatile(
        "mma.sync.aligned.m16n8k16.row.col.f32.f16.f16.f32 "
        "{%0,%1,%2,%3}, {%4,%5,%6,%7}, {%8,%9}, {%0,%1,%2,%3};\n"
        : "+f"(c0), "+f"(c1), "+f"(c2), "+f"(c3)
        : "r"(a0), "r"(a1), "r"(a2), "r"(a3), "r"(b0), "r"(b1));
}

// ---------------- prep: gate + Wt->fp16 ----------------
__global__ void k_misc(const float* __restrict__ sparse_var, const float* __restrict__ Wt) {
    int i = blockIdx.x * blockDim.x + threadIdx.x;
    int stride = gridDim.x * blockDim.x;
    for (int j = i; j < NF * NE; j += stride) {
        float s = 1.f / (1.f + expf(-15.f * sparse_var[j]));
        g_sv[j] = (s > 0.001f) ? s : 0.f;
    }
    for (int j = i; j < NF * NE * NE; j += stride)
        g_Wth[j] = __float2half(Wt[j]);
}

// ---------------- prep: fold BN scale into W (fp16) and bias (fp32) ----------------
__device__ __forceinline__ void fold_body(const float* __restrict__ W, const float* __restrict__ b,
                                          const float* __restrict__ g, const float* __restrict__ be,
                                          __half* Wo, float* bo, int total) {
    const float BNI = 0.9999950000374997f;  // 1/sqrt(1+1e-5)
    int i = blockIdx.x * blockDim.x + threadIdx.x;
    int stride = gridDim.x * blockDim.x;
    for (int k = i; k < total; k += stride) {
        int j = k % ND;
        Wo[k] = __float2half(W[k] * (BNI * g[j]));
        if (k < ND) bo[k] = b[k] * (BNI * g[k]) + be[k];
    }
}
__global__ void k_fold1(const float* W, const float* b, const float* g, const float* be) {
    fold_body(W, b, g, be, g_W1h, g_bf1, FE * ND);
}
__global__ void k_fold2(const float* W, const float* b, const float* g, const float* be) {
    fold_body(W, b, g, be, g_W2h, g_bf2, ND * ND);
}
__global__ void k_fold3(const float* W, const float* b, const float* g, const float* be) {
    fold_body(W, b, g, be, g_W3h, g_bf3, ND * ND);
}

// ---------------- gather + gate -> fp16 embed_x ----------------
__global__ void k_gather(const int* __restrict__ x, const float* __restrict__ emb) {
    int gw = (blockIdx.x * blockDim.x + threadIdx.x) >> 5;
    int lane = threadIdx.x & 31;
    if (gw >= BATCH * NF) return;
    int b = gw / NF;
    int f = gw - b * NF;
    int idx = x[b * NF + f] + f * VOC;
    const float2* row = (const float2*)(emb + (size_t)idx * NE);
    const float2* svp = (const float2*)(g_sv + f * NE);
    float2 v = row[lane];
    float2 s = svp[lane];
    __half2 h = __floats2half2_rn(v.x * s.x, v.y * s.y);
    *(__half2*)(g_embed + (size_t)b * FE + f * NE + lane * 2) = h;
}

// ---------------- per-field linear + FM (never materializes trans) ----------------
// block: 128 thr (4 warps), tile 64 samples x 64 out-cols; loop over 39 fields
__global__ __launch_bounds__(128) void k_trans_fm(const float* __restrict__ bt) {
    __shared__ __half As[64 * 72];
    __shared__ __half Bs[64 * 72];
    __shared__ float btS[FE];
    int t = threadIdx.x, w = t >> 5, lane = t & 31, g = lane >> 2, c = lane & 3;
    int m0 = blockIdx.x * 64;
    int rw = w * 16;
    for (int i = t; i < FE; i += 128) btS[i] = bt[i];

    float S[8][4];
    float q0 = 0.f, q1 = 0.f;
#pragma unroll
    for (int j = 0; j < 8; j++)
#pragma unroll
        for (int p = 0; p < 4; p++) S[j][p] = 0.f;

    int lr = t >> 1;            // 0..63 row for staging
    int lc = (t & 1) * 32;      // 0 or 32

    for (int f = 0; f < NF; f++) {
        // stage embed slice (64x64 fp16) and Wt_f (64x64 fp16, [o][i] layout)
        {
            const uint4* sa = (const uint4*)(g_embed + (size_t)(m0 + lr) * FE + f * NE + lc);
            uint4* da = (uint4*)(As + lr * 72 + lc);
            da[0] = sa[0]; da[1] = sa[1]; da[2] = sa[2]; da[3] = sa[3];
            const uint4* sb = (const uint4*)(g_Wth + f * (NE * NE) + lr * NE + lc);
            uint4* db = (uint4*)(Bs + lr * 72 + lc);
            db[0] = sb[0]; db[1] = sb[1]; db[2] = sb[2]; db[3] = sb[3];
        }
        __syncthreads();

        float acc[8][4];
#pragma unroll
        for (int j = 0; j < 8; j++)
#pragma unroll
            for (int p = 0; p < 4; p++) acc[j][p] = 0.f;

#pragma unroll
        for (int kk = 0; kk < 4; kk++) {
            int kb = kk * 16;
            uint32_t a0 = *(const uint32_t*)&As[(rw + g) * 72 + kb + 2 * c];
            uint32_t a1 = *(const uint32_t*)&As[(rw + 8 + g) * 72 + kb + 2 * c];
            uint32_t a2 = *(const uint32_t*)&As[(rw + g) * 72 + kb + 2 * c + 8];
            uint32_t a3 = *(const uint32_t*)&As[(rw + 8 + g) * 72 + kb + 2 * c + 8];
#pragma unroll
            for (int j = 0; j < 8; j++) {
                int col = j * 8 + g;
                uint32_t b0 = *(const uint32_t*)&Bs[col * 72 + kb + 2 * c];
                uint32_t b1 = *(const uint32_t*)&Bs[col * 72 + kb + 2 * c + 8];
                mma16816(acc[j][0], acc[j][1], acc[j][2], acc[j][3], a0, a1, a2, a3, b0, b1);
            }
        }
        // epilogue for this field: add bias, accumulate S and Q
#pragma unroll
        for (int j = 0; j < 8; j++) {
            int col = j * 8 + 2 * c;
            float bb0 = btS[f * NE + col];
            float bb1 = btS[f * NE + col + 1];
            float t0 = acc[j][0] + bb0;
            float t1 = acc[j][1] + bb1;
            float t2 = acc[j][2] + bb0;
            float t3 = acc[j][3] + bb1;
            S[j][0] += t0; S[j][1] += t1; S[j][2] += t2; S[j][3] += t3;
            q0 += t0 * t0 + t1 * t1;
            q1 += t2 * t2 + t3 * t3;
        }
        __syncthreads();
    }

    float s20 = 0.f, s21 = 0.f;
#pragma unroll
    for (int j = 0; j < 8; j++) {
        s20 += S[j][0] * S[j][0] + S[j][1] * S[j][1];
        s21 += S[j][2] * S[j][2] + S[j][3] * S[j][3];
    }
    // reduce over the 4 lanes of the quad-group (lanes 4g..4g+3)
#pragma unroll
    for (int m = 1; m <= 2; m <<= 1) {
        s20 += __shfl_xor_sync(0xffffffffu, s20, m);
        s21 += __shfl_xor_sync(0xffffffffu, s21, m);
        q0  += __shfl_xor_sync(0xffffffffu, q0, m);
        q1  += __shfl_xor_sync(0xffffffffu, q1, m);
    }
    if (c == 0) {
        int r0 = m0 + rw + g;
        g_scalar[r0] = 0.5f * (s20 - q0);
        g_scalar[r0 + 8] = 0.5f * (s21 - q1);
    }
}

// ---------------- tiled fp16 GEMM + bias + ReLU -> fp16 ----------------
// block: 256 thr (8 warps, 4x2), tile 128(M) x 64(N), k-step 16. M=16384, N=400.
__device__ __forceinline__ void gemm_body(const __half* __restrict__ A,
                                          const __half* __restrict__ Bm,
                                          const float* __restrict__ bias,
                                          __half* __restrict__ C, int K) {
    __shared__ __half As[128 * 24];
    __shared__ __half Bs[64 * 24];
    const int N = ND;
    int t = threadIdx.x, w = t >> 5, lane = t & 31, g = lane >> 2, c = lane & 3;
    int wm = w & 3, wn = w >> 2;
    int n0 = blockIdx.x * 64, m0 = blockIdx.y * 128;

    float acc[2][4][4];
#pragma unroll
    for (int i = 0; i < 2; i++)
#pragma unroll
        for (int j = 0; j < 4; j++)
#pragma unroll
            for (int p = 0; p < 4; p++) acc[i][j][p] = 0.f;

    int ar = t >> 1, ak = (t & 1) * 8;
    int bk = t >> 4, bn4 = (t & 15) * 4;
    int nk = K >> 4;

    for (int ks = 0; ks < nk; ks++) {
        int k0 = ks << 4;
        *(uint4*)&As[ar * 24 + ak] = *(const uint4*)&A[(size_t)(m0 + ar) * K + k0 + ak];
        uint2 bv = make_uint2(0u, 0u);
        int gcol = n0 + bn4;
        if (gcol < N) bv = *(const uint2*)&Bm[(size_t)(k0 + bk) * N + gcol];
        const __half* bh = (const __half*)&bv;
        Bs[(bn4 + 0) * 24 + bk] = bh[0];
        Bs[(bn4 + 1) * 24 + bk] = bh[1];
        Bs[(bn4 + 2) * 24 + bk] = bh[2];
        Bs[(bn4 + 3) * 24 + bk] = bh[3];
        __syncthreads();

        uint32_t a[2][4], bf[4][2];
#pragma unroll
        for (int mi = 0; mi < 2; mi++) {
            int rr = wm * 32 + mi * 16;
            a[mi][0] = *(const uint32_t*)&As[(rr + g) * 24 + 2 * c];
            a[mi][1] = *(const uint32_t*)&As[(rr + 8 + g) * 24 + 2 * c];
            a[mi][2] = *(const uint32_t*)&As[(rr + g) * 24 + 2 * c + 8];
            a[mi][3] = *(const uint32_t*)&As[(rr + 8 + g) * 24 + 2 * c + 8];
        }
#pragma unroll
        for (int j = 0; j < 4; j++) {
            int col = wn * 32 + j * 8 + g;
            bf[j][0] = *(const uint32_t*)&Bs[col * 24 + 2 * c];
            bf[j][1] = *(const uint32_t*)&Bs[col * 24 + 2 * c + 8];
        }
#pragma unroll
        for (int mi = 0; mi < 2; mi++)
#pragma unroll
            for (int j = 0; j < 4; j++)
                mma16816(acc[mi][j][0], acc[mi][j][1], acc[mi][j][2], acc[mi][j][3],
                         a[mi][0], a[mi][1], a[mi][2], a[mi][3], bf[j][0], bf[j][1]);
        __syncthreads();
    }

#pragma unroll
    for (int mi = 0; mi < 2; mi++) {
#pragma unroll
        for (int j = 0; j < 4; j++) {
            int col = n0 + wn * 32 + j * 8 + 2 * c;
            if (col < N) {
                float b0v = bias[col], b1v = bias[col + 1];
                int r0 = m0 + wm * 32 + mi * 16 + g;
                float v0 = fmaxf(acc[mi][j][0] + b0v, 0.f);
                float v1 = fmaxf(acc[mi][j][1] + b1v, 0.f);
                *(__half2*)&C[(size_t)r0 * N + col] = __floats2half2_rn(v0, v1);
                float v2 = fmaxf(acc[mi][j][2] + b0v, 0.f);
                float v3 = fmaxf(acc[mi][j][3] + b1v, 0.f);
                *(__half2*)&C[(size_t)(r0 + 8) * N + col] = __floats2half2_rn(v2, v3);
            }
        }
    }
}
__global__ __launch_bounds__(256) void k_mlp1() { gemm_body(g_embed, g_W1h, g_bf1, g_h1, FE); }
__global__ __launch_bounds__(256) void k_mlp2() { gemm_body(g_h1, g_W2h, g_bf2, g_h2, ND); }
__global__ __launch_bounds__(256) void k_mlp3() { gemm_body(g_h2, g_W3h, g_bf3, g_h3, ND); }

// ---------------- final: out-proj dot + deterministic lin gather + sigmoid ----------------
__global__ void k_final(const int* __restrict__ x, const float* __restrict__ lin_table,
                        const float* __restrict__ lin_bias, const float* __restrict__ Wout,
                        const float* __restrict__ bout, float* __restrict__ out) {
    int gw = (blockIdx.x * blockDim.x + threadIdx.x) >> 5;
    int lane = threadIdx.x & 31;
    if (gw >= BATCH) return;
    const __half* h = g_h3 + (size_t)gw * ND;
    float acc = 0.f;
    for (int j = lane; j < ND; j += 32)
        acc += __half2float(h[j]) * Wout[j];
    for (int j = lane; j < NF; j += 32)
        acc += lin_table[x[gw * NF + j] + j * VOC];
#pragma unroll
    for (int m = 16; m; m >>= 1) acc += __shfl_xor_sync(0xffffffffu, acc, m);
    if (lane == 0) {
        float z = g_scalar[gw] + acc + bout[0] + lin_bias[0];
        out[gw] = 1.f / (1.f + expf(-z));
    }
}

// ---------------- launch ----------------
extern "C" void kernel_launch(void* const* d_in, const int* in_sizes, int n_in,
                              void* d_out, int out_size) {
    const int*   x          = (const int*)d_in[0];
    const float* emb_table  = (const float*)d_in[1];
    const float* lin_table  = (const float*)d_in[2];
    const float* lin_bias   = (const float*)d_in[3];
    const float* sparse_var = (const float*)d_in[4];
    const float* Wt         = (const float*)d_in[5];
    const float* bt         = (const float*)d_in[6];
    const float* W1 = (const float*)d_in[7],  *b1 = (const float*)d_in[8];
    const float* g1 = (const float*)d_in[9],  *be1 = (const float*)d_in[10];
    const float* W2 = (const float*)d_in[11], *b2 = (const float*)d_in[12];
    const float* g2 = (const float*)d_in[13], *be2 = (const float*)d_in[14];
    const float* W3 = (const float*)d_in[15], *b3 = (const float*)d_in[16];
    const float* g3 = (const float*)d_in[17], *be3 = (const float*)d_in[18];
    const float* Wout = (const float*)d_in[19], *bout = (const float*)d_in[20];
    float* out = (float*)d_out;

    k_misc<<<624, 256>>>(sparse_var, Wt);
    k_fold1<<<976, 256>>>(W1, b1, g1, be1);
    k_fold2<<<160, 256>>>(W2, b2, g2, be2);
    k_fold3<<<160, 256>>>(W3, b3, g3, be3);
    k_gather<<<(BATCH * NF * 32) / 256, 256>>>(x, emb_table);
    k_trans_fm<<<BATCH / 64, 128>>>(bt);
    k_mlp1<<<dim3(7, BATCH / 128), 256>>>();
    k_mlp2<<<dim3(7, BATCH / 128), 256>>>();
    k_mlp3<<<dim3(7, BATCH / 128), 256>>>();
    k_final<<<(BATCH * 32) / 256, 256>>>(x, lin_table, lin_bias, Wout, bout, out);
}

// round 9
// speedup vs baseline: 1.4800x; 1.4800x over previous
#include <cuda_runtime.h>
#include <cuda_fp16.h>
#include <cstdint>
#include <cstddef>

#define BATCH 16384
#define NF 39
#define NE 64
#define FE 2496            // NF*NE
#define ND 400
#define NPAD 512           // padded N (zero rows) for clean 128-wide column tiles
#define VOC 26000

// ---------------- device scratch (static: no allocations allowed) ----------------
static __device__ __align__(128) __half g_embed[(size_t)BATCH * FE + 256];
static __device__ __align__(128) __half g_h1[(size_t)BATCH * ND + 256];
static __device__ __align__(128) __half g_h2[(size_t)BATCH * ND + 256];
static __device__ __align__(128) __half g_h3[(size_t)BATCH * ND + 256];
static __device__ float  g_scalar[BATCH];
static __device__ __align__(128) __half g_W1t[(size_t)NPAD * FE + 256];   // [n][k], BN folded, zero pad rows
static __device__ __align__(128) __half g_W2t[(size_t)NPAD * ND + 256];
static __device__ __align__(128) __half g_W3t[(size_t)NPAD * ND + 256];
static __device__ __align__(128) __half g_Wth[NF * NE * NE];
static __device__ float  g_bf1[ND], g_bf2[ND], g_bf3[ND];
static __device__ float  g_sv[NF * NE];

// ---------------- helpers ----------------
__device__ __forceinline__ uint32_t smem_u32(const void* p) {
    uint32_t a;
    asm("{ .reg .u64 t; cvta.to.shared.u64 t, %1; cvt.u32.u64 %0, t; }" : "=r"(a) : "l"(p));
    return a;
}

__device__ __forceinline__ void mma16816(float& c0, float& c1, float& c2, float& c3,
                                         uint32_t a0, uint32_t a1, uint32_t a2, uint32_t a3,
                                         uint32_t b0, uint32_t b1) {
    asm volatile(
        "mma.sync.aligned.m16n8k16.row.col.f32.f16.f16.f32 "
        "{%0,%1,%2,%3}, {%4,%5,%6,%7}, {%8,%9}, {%0,%1,%2,%3};\n"
        : "+f"(c0), "+f"(c1), "+f"(c2), "+f"(c3)
        : "r"(a0), "r"(a1), "r"(a2), "r"(a3), "r"(b0), "r"(b1));
}

// ---------------- prep: gate + Wt->fp16 ----------------
__global__ void k_misc(const float* __restrict__ sparse_var, const float* __restrict__ Wt) {
    int i = blockIdx.x * blockDim.x + threadIdx.x;
    int stride = gridDim.x * blockDim.x;
    for (int j = i; j < NF * NE; j += stride) {
        float s = 1.f / (1.f + expf(-15.f * sparse_var[j]));
        g_sv[j] = (s > 0.001f) ? s : 0.f;
    }
    for (int j = i; j < NF * NE * NE; j += stride)
        g_Wth[j] = __float2half(Wt[j]);
}

// ---------------- prep: transpose W to [n][k] fp16 with BN fold + zero pad rows ----------------
// NOTE: output arrays resolved INSIDE device code (passing __device__ symbols
// from host silently writes the host ATS shadow on GB300 — the R5-R8 bug).
__global__ void k_foldT(int layer, const float* __restrict__ W, const float* __restrict__ b,
                        const float* __restrict__ g, const float* __restrict__ be, int K) {
    __half* WtO; float* bO;
    if (layer == 0)      { WtO = g_W1t; bO = g_bf1; }
    else if (layer == 1) { WtO = g_W2t; bO = g_bf2; }
    else                 { WtO = g_W3t; bO = g_bf3; }

    __shared__ float tile[32][33];
    const float BNI = 0.9999950000374997f;
    int kb = blockIdx.x * 32, nb = blockIdx.y * 32;
    int tx = threadIdx.x, ty = threadIdx.y;   // (32, 8)
#pragma unroll
    for (int i = ty; i < 32; i += 8) {
        int k = kb + i, n = nb + tx;
        tile[i][tx] = (k < K && n < ND) ? W[(size_t)k * ND + n] : 0.f;
    }
    __syncthreads();
#pragma unroll
    for (int i = ty; i < 32; i += 8) {
        int n = nb + i, k = kb + tx;
        if (n < NPAD && k < K) {
            float sc = (n < ND) ? (BNI * g[n]) : 0.f;
            WtO[(size_t)n * K + k] = __float2half(tile[tx][i] * sc);
        }
    }
    if (blockIdx.x == 0 && ty == 0) {
        int n = nb + tx;
        if (n < ND) bO[n] = b[n] * (BNI * g[n]) + be[n];
    }
}

// ---------------- gather + gate -> fp16 embed_x ----------------
__global__ void k_gather(const int* __restrict__ x, const float* __restrict__ emb) {
    int gw = (blockIdx.x * blockDim.x + threadIdx.x) >> 5;
    int lane = threadIdx.x & 31;
    if (gw >= BATCH * NF) return;
    int b = gw / NF;
    int f = gw - b * NF;
    int idx = x[b * NF + f] + f * VOC;
    const float2* row = (const float2*)(emb + (size_t)idx * NE);
    const float2* svp = (const float2*)(g_sv + f * NE);
    float2 v = row[lane];
    float2 s = svp[lane];
    __half2 h = __floats2half2_rn(v.x * s.x, v.y * s.y);
    *(__half2*)(g_embed + (size_t)b * FE + f * NE + lane * 2) = h;
}

// ---------------- per-field linear + FM (never materializes trans) ----------------
__global__ __launch_bounds__(128) void k_trans_fm(const float* __restrict__ bt) {
    __shared__ __half As[64 * 72];
    __shared__ __half Bs[64 * 72];
    __shared__ float btS[FE];
    int t = threadIdx.x, w = t >> 5, lane = t & 31, g = lane >> 2, c = lane & 3;
    int m0 = blockIdx.x * 64;
    int rw = w * 16;
    for (int i = t; i < FE; i += 128) btS[i] = bt[i];

    float S[8][4];
    float q0 = 0.f, q1 = 0.f;
#pragma unroll
    for (int j = 0; j < 8; j++)
#pragma unroll
        for (int p = 0; p < 4; p++) S[j][p] = 0.f;

    int lr = t >> 1;
    int lc = (t & 1) * 32;

    for (int f = 0; f < NF; f++) {
        {
            const uint4* sa = (const uint4*)(g_embed + (size_t)(m0 + lr) * FE + f * NE + lc);
            uint4* da = (uint4*)(As + lr * 72 + lc);
            da[0] = sa[0]; da[1] = sa[1]; da[2] = sa[2]; da[3] = sa[3];
            const uint4* sb = (const uint4*)(g_Wth + f * (NE * NE) + lr * NE + lc);
            uint4* db = (uint4*)(Bs + lr * 72 + lc);
            db[0] = sb[0]; db[1] = sb[1]; db[2] = sb[2]; db[3] = sb[3];
        }
        __syncthreads();

        float acc[8][4];
#pragma unroll
        for (int j = 0; j < 8; j++)
#pragma unroll
            for (int p = 0; p < 4; p++) acc[j][p] = 0.f;

#pragma unroll
        for (int kk = 0; kk < 4; kk++) {
            int kb = kk * 16;
            uint32_t a0 = *(const uint32_t*)&As[(rw + g) * 72 + kb + 2 * c];
            uint32_t a1 = *(const uint32_t*)&As[(rw + 8 + g) * 72 + kb + 2 * c];
            uint32_t a2 = *(const uint32_t*)&As[(rw + g) * 72 + kb + 2 * c + 8];
            uint32_t a3 = *(const uint32_t*)&As[(rw + 8 + g) * 72 + kb + 2 * c + 8];
#pragma unroll
            for (int j = 0; j < 8; j++) {
                int col = j * 8 + g;
                uint32_t b0 = *(const uint32_t*)&Bs[col * 72 + kb + 2 * c];
                uint32_t b1 = *(const uint32_t*)&Bs[col * 72 + kb + 2 * c + 8];
                mma16816(acc[j][0], acc[j][1], acc[j][2], acc[j][3], a0, a1, a2, a3, b0, b1);
            }
        }
#pragma unroll
        for (int j = 0; j < 8; j++) {
            int col = j * 8 + 2 * c;
            float bb0 = btS[f * NE + col];
            float bb1 = btS[f * NE + col + 1];
            float t0 = acc[j][0] + bb0;
            float t1 = acc[j][1] + bb1;
            float t2 = acc[j][2] + bb0;
            float t3 = acc[j][3] + bb1;
            S[j][0] += t0; S[j][1] += t1; S[j][2] += t2; S[j][3] += t3;
            q0 += t0 * t0 + t1 * t1;
            q1 += t2 * t2 + t3 * t3;
        }
        __syncthreads();
    }

    float s20 = 0.f, s21 = 0.f;
#pragma unroll
    for (int j = 0; j < 8; j++) {
        s20 += S[j][0] * S[j][0] + S[j][1] * S[j][1];
        s21 += S[j][2] * S[j][2] + S[j][3] * S[j][3];
    }
#pragma unroll
    for (int m = 1; m <= 2; m <<= 1) {
        s20 += __shfl_xor_sync(0xffffffffu, s20, m);
        s21 += __shfl_xor_sync(0xffffffffu, s21, m);
        q0  += __shfl_xor_sync(0xffffffffu, q0, m);
        q1  += __shfl_xor_sync(0xffffffffu, q1, m);
    }
    if (c == 0) {
        int r0 = m0 + rw + g;
        g_scalar[r0] = 0.5f * (s20 - q0);
        g_scalar[r0 + 8] = 0.5f * (s21 - q1);
    }
}

// ---------------- pipelined mma.sync GEMM: [16384 x K] @ Bt[512 x K]^T + bias + ReLU ----------------
// CTA: 256 thr (8 warps = 4M x 2N), tile 128M x 128N, warp tile 32x64.
// K in 32-wide chunks, 2-stage cp.async pipeline, STATIC shared (40 KB).
#define BK 32
#define SR 40               // smem row stride in halves (32 + 8 pad)

__device__ __forceinline__ void stage32(const __half* __restrict__ A,
                                        const __half* __restrict__ Bt, int K,
                                        int m0, int n0, int k0,
                                        uint32_t sa, uint32_t sb, int tid) {
#pragma unroll
    for (int i = 0; i < 2; i++) {               // A: 128 rows x 4 x 16B = 512 pieces
        int p = tid + i * 256;
        int r = p >> 2, s = p & 3;
        uint32_t dst = sa + r * (SR * 2) + s * 16;
        const void* src = A + (size_t)(m0 + r) * K + k0 + s * 8;
        asm volatile("cp.async.cg.shared.global [%0], [%1], 16;\n" :: "r"(dst), "l"(src));
    }
#pragma unroll
    for (int i = 0; i < 2; i++) {               // B: 128 rows x 4 x 16B = 512 pieces
        int p = tid + i * 256;
        int r = p >> 2, s = p & 3;
        uint32_t dst = sb + r * (SR * 2) + s * 16;
        const void* src = Bt + (size_t)(n0 + r) * K + k0 + s * 8;
        asm volatile("cp.async.cg.shared.global [%0], [%1], 16;\n" :: "r"(dst), "l"(src));
    }
    asm volatile("cp.async.commit_group;\n" ::: "memory");
}

__global__ __launch_bounds__(256, 2) void k_mlp(int layer) {
    const __half* A; const __half* Bt; const float* bias; __half* Out; int K;
    if (layer == 0)      { A = g_embed; Bt = g_W1t; bias = g_bf1; Out = g_h1; K = FE; }
    else if (layer == 1) { A = g_h1;    Bt = g_W2t; bias = g_bf2; Out = g_h2; K = ND; }
    else                 { A = g_h2;    Bt = g_W3t; bias = g_bf3; Out = g_h3; K = ND; }

    __shared__ __half As[2][128 * SR];
    __shared__ __half Bs[2][128 * SR];
    uint32_t saA[2] = { smem_u32(As[0]), smem_u32(As[1]) };
    uint32_t saB[2] = { smem_u32(Bs[0]), smem_u32(Bs[1]) };

    const int tid = threadIdx.x, w = tid >> 5, lane = tid & 31;
    const int g = lane >> 2, cq = lane & 3;
    const int wm = w >> 1, wn = w & 1;            // 4M x 2N warps
    const int m0 = blockIdx.y * 128, n0 = blockIdx.x * 128;

    float acc[2][8][4];
#pragma unroll
    for (int mt = 0; mt < 2; mt++)
#pragma unroll
        for (int nt = 0; nt < 8; nt++)
#pragma unroll
            for (int p = 0; p < 4; p++) acc[mt][nt][p] = 0.f;

    const int nc = (K + BK - 1) / BK;
    stage32(A, Bt, K, m0, n0, 0, saA[0], saB[0], tid);

    for (int ch = 0; ch < nc; ch++) {
        if (ch + 1 < nc) {
            stage32(A, Bt, K, m0, n0, (ch + 1) * BK, saA[(ch + 1) & 1], saB[(ch + 1) & 1], tid);
            asm volatile("cp.async.wait_group 1;\n" ::: "memory");
        } else {
            asm volatile("cp.async.wait_group 0;\n" ::: "memory");
        }
        __syncthreads();

        const __half* Ac = As[ch & 1];
        const __half* Bc = Bs[ch & 1];
        const int kmax = K - ch * BK;
#pragma unroll
        for (int kk = 0; kk < 2; kk++) {
            if (kk * 16 < kmax) {
                const int kb = kk * 16;
                uint32_t a[2][4];
#pragma unroll
                for (int mt = 0; mt < 2; mt++) {
                    int rb = wm * 32 + mt * 16;
                    a[mt][0] = *(const uint32_t*)&Ac[(rb + g) * SR + kb + 2 * cq];
                    a[mt][1] = *(const uint32_t*)&Ac[(rb + 8 + g) * SR + kb + 2 * cq];
                    a[mt][2] = *(const uint32_t*)&Ac[(rb + g) * SR + kb + 2 * cq + 8];
                    a[mt][3] = *(const uint32_t*)&Ac[(rb + 8 + g) * SR + kb + 2 * cq + 8];
                }
#pragma unroll
                for (int nt = 0; nt < 8; nt++) {
                    int col = wn * 64 + nt * 8 + g;
                    uint32_t b0 = *(const uint32_t*)&Bc[col * SR + kb + 2 * cq];
                    uint32_t b1 = *(const uint32_t*)&Bc[col * SR + kb + 2 * cq + 8];
#pragma unroll
                    for (int mt = 0; mt < 2; mt++)
                        mma16816(acc[mt][nt][0], acc[mt][nt][1], acc[mt][nt][2], acc[mt][nt][3],
                                 a[mt][0], a[mt][1], a[mt][2], a[mt][3], b0, b1);
                }
            }
        }
        __syncthreads();
    }

    // epilogue: bias + ReLU -> fp16
#pragma unroll
    for (int nt = 0; nt < 8; nt++) {
        int col = n0 + wn * 64 + nt * 8 + 2 * cq;
        if (col < ND) {
            float b0v = bias[col], b1v = bias[col + 1];
#pragma unroll
            for (int mt = 0; mt < 2; mt++) {
                int r0 = m0 + wm * 32 + mt * 16 + g;
                float v0 = fmaxf(acc[mt][nt][0] + b0v, 0.f);
                float v1 = fmaxf(acc[mt][nt][1] + b1v, 0.f);
                *(__half2*)&Out[(size_t)r0 * ND + col] = __floats2half2_rn(v0, v1);
                float v2 = fmaxf(acc[mt][nt][2] + b0v, 0.f);
                float v3 = fmaxf(acc[mt][nt][3] + b1v, 0.f);
                *(__half2*)&Out[(size_t)(r0 + 8) * ND + col] = __floats2half2_rn(v2, v3);
            }
        }
    }
}

// ---------------- final: out-proj dot + deterministic lin gather + sigmoid ----------------
__global__ void k_final(const int* __restrict__ x, const float* __restrict__ lin_table,
                        const float* __restrict__ lin_bias, const float* __restrict__ Wout,
                        const float* __restrict__ bout, float* __restrict__ out) {
    int gw = (blockIdx.x * blockDim.x + threadIdx.x) >> 5;
    int lane = threadIdx.x & 31;
    if (gw >= BATCH) return;
    const __half* h = g_h3 + (size_t)gw * ND;
    float acc = 0.f;
    for (int j = lane; j < ND; j += 32)
        acc += __half2float(h[j]) * Wout[j];
    for (int j = lane; j < NF; j += 32)
        acc += lin_table[x[gw * NF + j] + j * VOC];
#pragma unroll
    for (int m = 16; m; m >>= 1) acc += __shfl_xor_sync(0xffffffffu, acc, m);
    if (lane == 0) {
        float z = g_scalar[gw] + acc + bout[0] + lin_bias[0];
        out[gw] = 1.f / (1.f + expf(-z));
    }
}

// ---------------- launch ----------------
extern "C" void kernel_launch(void* const* d_in, const int* in_sizes, int n_in,
                              void* d_out, int out_size) {
    const int*   x          = (const int*)d_in[0];
    const float* emb_table  = (const float*)d_in[1];
    const float* lin_table  = (const float*)d_in[2];
    const float* lin_bias   = (const float*)d_in[3];
    const float* sparse_var = (const float*)d_in[4];
    const float* Wt         = (const float*)d_in[5];
    const float* bt         = (const float*)d_in[6];
    const float* W1 = (const float*)d_in[7],  *b1 = (const float*)d_in[8];
    const float* g1 = (const float*)d_in[9],  *be1 = (const float*)d_in[10];
    const float* W2 = (const float*)d_in[11], *b2 = (const float*)d_in[12];
    const float* g2 = (const float*)d_in[13], *be2 = (const float*)d_in[14];
    const float* W3 = (const float*)d_in[15], *b3 = (const float*)d_in[16];
    const float* g3 = (const float*)d_in[17], *be3 = (const float*)d_in[18];
    const float* Wout = (const float*)d_in[19], *bout = (const float*)d_in[20];
    float* out = (float*)d_out;

    k_misc<<<624, 256>>>(sparse_var, Wt);
    {
        dim3 blk(32, 8);
        k_foldT<<<dim3(FE / 32, NPAD / 32), blk>>>(0, W1, b1, g1, be1, FE);
        k_foldT<<<dim3(13, NPAD / 32), blk>>>(1, W2, b2, g2, be2, ND);
        k_foldT<<<dim3(13, NPAD / 32), blk>>>(2, W3, b3, g3, be3, ND);
    }
    k_gather<<<(BATCH * NF * 32) / 256, 256>>>(x, emb_table);
    k_trans_fm<<<BATCH / 64, 128>>>(bt);
    k_mlp<<<dim3(4, BATCH / 128), 256>>>(0);
    k_mlp<<<dim3(4, BATCH / 128), 256>>>(1);
    k_mlp<<<dim3(4, BATCH / 128), 256>>>(2);
    k_final<<<(BATCH * 32) / 256, 256>>>(x, lin_table, lin_bias, Wout, bout, out);
}